// round 5
// baseline (speedup 1.0000x reference)
#include <cuda_runtime.h>
#include <cuda_fp16.h>

#define BB   32      // batch
#define NN   2048    // input capsules
#define IL   32      // input capsule length
#define CC   32      // output capsules
#define LL   32      // output capsule length
#define KK   1024    // CC*LL
#define NCH1 128     // j-chunks for u/s0 kernel (16 j each)
#define PCH  32      // pass CTAs per b (each CTA covers 64 j)

typedef unsigned long long ull;

// Scratch (device globals: allocation-free rule)
__device__ __half g_uh [(size_t)BB * NN * KK];    // 128 MB prediction tensor (fp16)
__device__ float  g_s0p[(size_t)BB * NCH1 * KK];  // s partials, round 0 (16 MB)
__device__ float  g_sp [(size_t)BB * PCH * KK];   // s partials, rounds 1/2 (4 MB)
__device__ float  g_v0 [BB * KK];
__device__ float  g_v1 [BB * KK];
__device__ float  g_dummy[1];

__device__ __forceinline__ void ffma2(ull& acc, ull a, ull b) {
    asm("fma.rn.f32x2 %0, %1, %2, %0;" : "+l"(acc) : "l"(a), "l"(b));
}
__device__ __forceinline__ void fadd2(ull& acc, ull a) {
    asm("add.rn.f32x2 %0, %1, %0;" : "+l"(acc) : "l"(a));
}
__device__ __forceinline__ float2 up2(ull v) {
    float2 f;
    asm("mov.b64 {%0, %1}, %2;" : "=f"(f.x), "=f"(f.y) : "l"(v));
    return f;
}

__global__ void k_dummy(float* p) { if (threadIdx.x == 0) p[0] = 0.f; }

// K1: u[b,j,k] = sum_i x[b,j,i]*W[j,i,k]; s0 partial = sum_j u / 32.
// CTA = (16-j chunk, k-quarter), processed as 4 sub-chunks of 4 j (x restaged
// per sub-chunk; s0 accumulated across all 16 -> s0p traffic 4x smaller).
// W streamed via explicit ring-4 register pipeline (8 LDG.128 in flight).
__global__ void __launch_bounds__(256, 2)
k1(const float* __restrict__ x, const float* __restrict__ Wt) {
    const int kg    = threadIdx.x & 63;
    const int bg    = threadIdx.x >> 6;
    const int chunk = blockIdx.x;          // 0..127
    const int kq    = blockIdx.y;          // 0..3, 256 k each
    __shared__ float2 xs[4][32][32];       // 32 KB x duplicated for f32x2

    ull s0[8][2];
#pragma unroll
    for (int bb = 0; bb < 8; bb++) { s0[bb][0] = s0[bb][1] = 0ull; }

    for (int sc = 0; sc < 4; sc++) {
        const int jb = chunk * 16 + sc * 4;

        __syncthreads();                   // xs reuse guard
#pragma unroll
        for (int r = 0; r < 16; r++) {
            int idx = threadIdx.x + 256 * r;
            int jl = idx >> 10, rem = idx & 1023;
            int b = rem >> 5, i = rem & 31;
            float v = x[((size_t)b * NN + jb + jl) * IL + i];
            xs[jl][b][i] = make_float2(v, v);
        }
        __syncthreads();

        // W base; pair p -> (j = p>>4, i = 2*(p&15))
        const ulonglong2* Wb =
            reinterpret_cast<const ulonglong2*>(Wt) +
            (size_t)jb * IL * 256 + (size_t)kq * 64 + kg;
#define PADDR(p) (Wb + ((size_t)((p) >> 4) * 8192 + (size_t)((p) & 15) * 512))

        ulonglong2 rw0[4], rw1[4];         // ring-4 of W pairs
#pragma unroll
        for (int pp = 0; pp < 4; pp++) { rw0[pp] = PADDR(pp)[0]; rw1[pp] = PADDR(pp)[256]; }

        ull acc[8][2];
#pragma unroll
        for (int bb = 0; bb < 8; bb++) { acc[bb][0] = acc[bb][1] = 0ull; }

        for (int j = 0; j < 4; j++) {
#pragma unroll
            for (int pr = 0; pr < 16; pr++) {
                const int p = j * 16 + pr;
                const int s = pr & 3;      // ring slot (16 % 4 == 0)
                ulonglong2 w0 = rw0[s], w1 = rw1[s];
                if (p + 4 < 64) { rw0[s] = PADDR(p + 4)[0]; rw1[s] = PADDR(p + 4)[256]; }
                const int i = pr * 2;
#pragma unroll
                for (int bb = 0; bb < 8; bb++) {
                    ulonglong2 xx = *reinterpret_cast<const ulonglong2*>(&xs[j][bg * 8 + bb][i]);
                    ffma2(acc[bb][0], w0.x, xx.x);
                    ffma2(acc[bb][1], w0.y, xx.x);
                    ffma2(acc[bb][0], w1.x, xx.y);
                    ffma2(acc[bb][1], w1.y, xx.y);
                }
            }
            // store u row (fp16), fold into s0, reset acc
            const size_t kbase = (size_t)kq * 256 + (size_t)kg * 4;
            const int jg = jb + j;
#pragma unroll
            for (int bb = 0; bb < 8; bb++) {
                const int b = bg * 8 + bb;
                float2 a0 = up2(acc[bb][0]), a1 = up2(acc[bb][1]);
                __half2 h0 = __floats2half2_rn(a0.x, a0.y);
                __half2 h1 = __floats2half2_rn(a1.x, a1.y);
                uint2 pk;
                pk.x = *reinterpret_cast<unsigned*>(&h0);
                pk.y = *reinterpret_cast<unsigned*>(&h1);
                *reinterpret_cast<uint2*>(g_uh + ((size_t)b * NN + jg) * KK + kbase) = pk;
                fadd2(s0[bb][0], acc[bb][0]);
                fadd2(s0[bb][1], acc[bb][1]);
                acc[bb][0] = acc[bb][1] = 0ull;
            }
        }
#undef PADDR
    }

    const float sc = 1.0f / 32.0f;         // softmax(0) coupling = 1/C
    const size_t kbase = (size_t)kq * 256 + (size_t)kg * 4;
#pragma unroll
    for (int bb = 0; bb < 8; bb++) {
        const int b = bg * 8 + bb;
        float2 a0 = up2(s0[bb][0]), a1 = up2(s0[bb][1]);
        float4 r = make_float4(a0.x * sc, a0.y * sc, a1.x * sc, a1.y * sc);
        *reinterpret_cast<float4*>(
            g_s0p + ((size_t)b * NCH1 + chunk) * KK + kbase) = r;
    }
}

// Routing pass, transpose-free. Lane t's uint4 group q (index t+32q of the
// u row) covers k = 8t+256q+e (e<8), all inside capsule c_q = (t>>2)+8q.
// Quad shfl (xor 1,2) completes each capsule dot; shfl xor 4,8,16 spans all
// 32 capsules for the softmax. v lives in TRANSPOSED smem (vs[(8q+e)*32+t])
// so lane reads are consecutive/conflict-free -> 32 fewer registers ->
// 2 CTAs/SM -> 2x memory-level parallelism vs round 4.
// NP=1: logits = u.v0.   NP=2: logits = u.(v0+v1).
#define PASS_BODY(BUF, JJ)                                                     \
    {                                                                          \
        float uf[32];                                                          \
        _Pragma("unroll")                                                      \
        for (int q = 0; q < 4; q++) {                                          \
            float2 f;                                                          \
            f = __half22float2(*reinterpret_cast<const __half2*>(&BUF[q].x));  \
            uf[8 * q + 0] = f.x; uf[8 * q + 1] = f.y;                          \
            f = __half22float2(*reinterpret_cast<const __half2*>(&BUF[q].y));  \
            uf[8 * q + 2] = f.x; uf[8 * q + 3] = f.y;                          \
            f = __half22float2(*reinterpret_cast<const __half2*>(&BUF[q].z));  \
            uf[8 * q + 4] = f.x; uf[8 * q + 5] = f.y;                          \
            f = __half22float2(*reinterpret_cast<const __half2*>(&BUF[q].w));  \
            uf[8 * q + 6] = f.x; uf[8 * q + 7] = f.y;                          \
        }                                                                      \
        if ((JJ) + 2 < 8) {                                                    \
            _Pragma("unroll")                                                  \
            for (int q = 0; q < 4; q++)                                        \
                BUF[q] = up[((JJ) + 2) * 128 + q * 32 + t];                    \
        }                                                                      \
        float d[4];                                                            \
        _Pragma("unroll")                                                      \
        for (int q = 0; q < 4; q++) {                                          \
            float a = 0.f, bq = 0.f;                                           \
            _Pragma("unroll")                                                  \
            for (int e = 0; e < 8; e += 2) {                                   \
                a  += uf[8 * q + e]     * vs[(8 * q + e) * 32 + t];            \
                bq += uf[8 * q + e + 1] * vs[(8 * q + e + 1) * 32 + t];        \
            }                                                                  \
            d[q] = a + bq;                                                     \
            d[q] += __shfl_xor_sync(0xffffffffu, d[q], 1);                     \
            d[q] += __shfl_xor_sync(0xffffffffu, d[q], 2);                     \
        }                                                                      \
        float m = fmaxf(fmaxf(d[0], d[1]), fmaxf(d[2], d[3]));                 \
        m = fmaxf(m, __shfl_xor_sync(0xffffffffu, m, 4));                      \
        m = fmaxf(m, __shfl_xor_sync(0xffffffffu, m, 8));                      \
        m = fmaxf(m, __shfl_xor_sync(0xffffffffu, m, 16));                     \
        float ce[4];                                                           \
        _Pragma("unroll")                                                      \
        for (int q = 0; q < 4; q++) ce[q] = __expf(d[q] - m);                  \
        float Z = (ce[0] + ce[1]) + (ce[2] + ce[3]);                           \
        Z += __shfl_xor_sync(0xffffffffu, Z, 4);                               \
        Z += __shfl_xor_sync(0xffffffffu, Z, 8);                               \
        Z += __shfl_xor_sync(0xffffffffu, Z, 16);                              \
        const float invZ = __fdividef(1.0f, Z);                                \
        _Pragma("unroll")                                                      \
        for (int q = 0; q < 4; q++) {                                          \
            const float cq = ce[q] * invZ;                                     \
            _Pragma("unroll")                                                  \
            for (int e = 0; e < 8; e++)                                        \
                sacc[8 * q + e] += cq * uf[8 * q + e];                         \
        }                                                                      \
    }

template <int NP>
__global__ void __launch_bounds__(256, 2)
k_pass(const float* __restrict__ vin0, const float* __restrict__ vin1,
       float* __restrict__ sp) {
    const int b = blockIdx.y;
    const int w = threadIdx.x >> 5;
    const int t = threadIdx.x & 31;

    __shared__ float vs[1024];         // transposed v: vs[k32*32+t] = v[8t+...]
    __shared__ float red[8][1032];     // CTA reduction (16B-aligned rows)

    // stage v transposed (NP==2 folds v0+v1)
    for (int idx = threadIdx.x; idx < 1024; idx += 256) {
        int k32 = idx >> 5, tt = idx & 31;
        int k = 8 * tt + 256 * (k32 >> 3) + (k32 & 7);
        float v = vin0[(size_t)b * KK + k];
        if (NP == 2) v += vin1[(size_t)b * KK + k];
        vs[idx] = v;
    }
    __syncthreads();

    float sacc[32];
#pragma unroll
    for (int l = 0; l < 32; l++) sacc[l] = 0.f;

    const int jbase = blockIdx.x * 64 + w * 8;   // 8 warps x 8 j = 64 j / CTA
    const uint4* up = reinterpret_cast<const uint4*>(g_uh + ((size_t)b * NN + jbase) * KK);

    uint4 r0[4], r1[4];
#pragma unroll
    for (int q = 0; q < 4; q++) r0[q] = up[q * 32 + t];          // j0
#pragma unroll
    for (int q = 0; q < 4; q++) r1[q] = up[128 + q * 32 + t];    // j1

    for (int jb = 0; jb < 8; jb += 2) {
        PASS_BODY(r0, jb)
        PASS_BODY(r1, jb + 1)
    }

    // CTA reduction across the 8 warps (natural k layout)
#pragma unroll
    for (int q = 0; q < 4; q++) {
        *reinterpret_cast<float4*>(&red[w][8 * t + 256 * q])     =
            make_float4(sacc[8 * q + 0], sacc[8 * q + 1], sacc[8 * q + 2], sacc[8 * q + 3]);
        *reinterpret_cast<float4*>(&red[w][8 * t + 256 * q + 4]) =
            make_float4(sacc[8 * q + 4], sacc[8 * q + 5], sacc[8 * q + 6], sacc[8 * q + 7]);
    }
    __syncthreads();

    float4 s = make_float4(0.f, 0.f, 0.f, 0.f);
#pragma unroll
    for (int ww = 0; ww < 8; ww++) {
        float4 p = *reinterpret_cast<const float4*>(&red[ww][4 * threadIdx.x]);
        s.x += p.x; s.y += p.y; s.z += p.z; s.w += p.w;
    }
    *reinterpret_cast<float4*>(sp + ((size_t)b * PCH + blockIdx.x) * KK + 4 * threadIdx.x) = s;
}

// Finalize: reduce NCH chunk partials + biases, squash -> v.
// One CTA (8 warps) per (b,c) for memory-level parallelism on the reduction.
template <int NCH>
__global__ void __launch_bounds__(256)
k_fin(const float* __restrict__ sp, const float* __restrict__ biases,
      float* __restrict__ vout) {
    const int bc = blockIdx.x;
    const int b = bc >> 5, c = bc & 31;
    const int w = threadIdx.x >> 5, lane = threadIdx.x & 31;

    float s = 0.f;
    const float* p = sp + (size_t)b * NCH * KK + c * LL + lane;
#pragma unroll 8
    for (int n = w; n < NCH; n += 8) s += p[(size_t)n * KK];

    __shared__ float red[8][32];
    red[w][lane] = s;
    __syncthreads();

    if (w == 0) {
        float v = biases[c * LL + lane];
#pragma unroll
        for (int ww = 0; ww < 8; ww++) v += red[ww][lane];
        float n2 = v * v;
#pragma unroll
        for (int o = 16; o; o >>= 1) n2 += __shfl_xor_sync(0xffffffffu, n2, o);
        const float nn = sqrtf(n2);
        const float f = n2 / (1.0f + n2) / (nn + 1e-7f);   // squash factor
        vout[(size_t)b * KK + c * LL + lane] = f * v;
    }
}

extern "C" void kernel_launch(void* const* d_in, const int* in_sizes, int n_in,
                              void* d_out, int out_size) {
    const float* x      = (const float*)d_in[0];  // [32,8,8,32,32] = [B,N,iL]
    const float* Wt     = (const float*)d_in[1];  // [2048,32,1024]
    const float* biases = (const float*)d_in[2];  // [32,32]
    float* out = (float*)d_out;                   // [32,32,32]

    float *s0p, *sp, *v0, *v1, *dm;
    cudaGetSymbolAddress((void**)&s0p, g_s0p);
    cudaGetSymbolAddress((void**)&sp,  g_sp);
    cudaGetSymbolAddress((void**)&v0,  g_v0);
    cudaGetSymbolAddress((void**)&v1,  g_v1);
    cudaGetSymbolAddress((void**)&dm,  g_dummy);

    k_dummy<<<1, 32>>>(dm);                              // launch 0 (ncu shim)
    k1<<<dim3(NCH1, 4), 256>>>(x, Wt);                   // launch 1
    k_fin<NCH1><<<BB * CC, 256>>>(s0p, biases, v0);      // launch 2
    k_pass<1><<<dim3(PCH, BB), 256>>>(v0, v0, sp);       // launch 3
    k_fin<PCH><<<BB * CC, 256>>>(sp, biases, v1);        // launch 4
    k_pass<2><<<dim3(PCH, BB), 256>>>(v0, v1, sp);       // launch 5
    k_fin<PCH><<<BB * CC, 256>>>(sp, biases, out);       // launch 6
}

// round 6
// speedup vs baseline: 1.1451x; 1.1451x over previous
#include <cuda_runtime.h>
#include <cuda_fp16.h>

#define BB   32      // batch
#define NN   2048    // input capsules
#define IL   32      // input capsule length
#define CC   32      // output capsules
#define LL   32      // output capsule length
#define KK   1024    // CC*LL
#define NCH1 128     // j-chunks for u/s0 kernel (16 j each)
#define PCH  32      // pass CTAs per b (each CTA covers 64 j)

typedef unsigned long long ull;

// Scratch (device globals: allocation-free rule)
__device__ __half g_uh [(size_t)BB * NN * KK];    // 128 MB prediction tensor (fp16)
__device__ float  g_s0p[(size_t)BB * NCH1 * KK];  // s partials, round 0 (16 MB)
__device__ float  g_sp [(size_t)BB * PCH * KK];   // s partials, rounds 1/2 (4 MB)
__device__ float  g_v0 [BB * KK];
__device__ float  g_v1 [BB * KK];
__device__ float  g_dummy[1];

__device__ __forceinline__ void ffma2(ull& acc, ull a, ull b) {
    asm("fma.rn.f32x2 %0, %1, %2, %0;" : "+l"(acc) : "l"(a), "l"(b));
}
__device__ __forceinline__ void fadd2(ull& acc, ull a) {
    asm("add.rn.f32x2 %0, %1, %0;" : "+l"(acc) : "l"(a));
}
__device__ __forceinline__ float2 up2(ull v) {
    float2 f;
    asm("mov.b64 {%0, %1}, %2;" : "=f"(f.x), "=f"(f.y) : "l"(v));
    return f;
}
__device__ __forceinline__ __half2 geth2(const uint4& v, int p) {
    unsigned u = (&v.x)[p];
    return *reinterpret_cast<const __half2*>(&u);
}

__global__ void k_dummy(float* p) { if (threadIdx.x == 0) p[0] = 0.f; }

// K1: u[b,j,k] = sum_i x[b,j,i]*W[j,i,k]; s0 partial = sum_j u / 32.
// CTA = (16-j chunk, k-quarter), processed as 4 sub-chunks of 4 j.
// W streamed via explicit ring-4 register pipeline (8 LDG.128 in flight).
__global__ void __launch_bounds__(256, 2)
k1(const float* __restrict__ x, const float* __restrict__ Wt) {
    const int kg    = threadIdx.x & 63;
    const int bg    = threadIdx.x >> 6;
    const int chunk = blockIdx.x;          // 0..127
    const int kq    = blockIdx.y;          // 0..3, 256 k each
    __shared__ float2 xs[4][32][32];       // 32 KB x duplicated for f32x2

    ull s0[8][2];
#pragma unroll
    for (int bb = 0; bb < 8; bb++) { s0[bb][0] = s0[bb][1] = 0ull; }

    for (int sc = 0; sc < 4; sc++) {
        const int jb = chunk * 16 + sc * 4;

        __syncthreads();                   // xs reuse guard
#pragma unroll
        for (int r = 0; r < 16; r++) {
            int idx = threadIdx.x + 256 * r;
            int jl = idx >> 10, rem = idx & 1023;
            int b = rem >> 5, i = rem & 31;
            float v = x[((size_t)b * NN + jb + jl) * IL + i];
            xs[jl][b][i] = make_float2(v, v);
        }
        __syncthreads();

        // W base; pair p -> (j = p>>4, i = 2*(p&15))
        const ulonglong2* Wb =
            reinterpret_cast<const ulonglong2*>(Wt) +
            (size_t)jb * IL * 256 + (size_t)kq * 64 + kg;
#define PADDR(p) (Wb + ((size_t)((p) >> 4) * 8192 + (size_t)((p) & 15) * 512))

        ulonglong2 rw0[4], rw1[4];         // ring-4 of W pairs
#pragma unroll
        for (int pp = 0; pp < 4; pp++) { rw0[pp] = PADDR(pp)[0]; rw1[pp] = PADDR(pp)[256]; }

        ull acc[8][2];
#pragma unroll
        for (int bb = 0; bb < 8; bb++) { acc[bb][0] = acc[bb][1] = 0ull; }

        for (int j = 0; j < 4; j++) {
#pragma unroll
            for (int pr = 0; pr < 16; pr++) {
                const int p = j * 16 + pr;
                const int s = pr & 3;      // ring slot (16 % 4 == 0)
                ulonglong2 w0 = rw0[s], w1 = rw1[s];
                if (p + 4 < 64) { rw0[s] = PADDR(p + 4)[0]; rw1[s] = PADDR(p + 4)[256]; }
                const int i = pr * 2;
#pragma unroll
                for (int bb = 0; bb < 8; bb++) {
                    ulonglong2 xx = *reinterpret_cast<const ulonglong2*>(&xs[j][bg * 8 + bb][i]);
                    ffma2(acc[bb][0], w0.x, xx.x);
                    ffma2(acc[bb][1], w0.y, xx.x);
                    ffma2(acc[bb][0], w1.x, xx.y);
                    ffma2(acc[bb][1], w1.y, xx.y);
                }
            }
            // store u row (fp16), fold into s0, reset acc
            const size_t kbase = (size_t)kq * 256 + (size_t)kg * 4;
            const int jg = jb + j;
#pragma unroll
            for (int bb = 0; bb < 8; bb++) {
                const int b = bg * 8 + bb;
                float2 a0 = up2(acc[bb][0]), a1 = up2(acc[bb][1]);
                __half2 h0 = __floats2half2_rn(a0.x, a0.y);
                __half2 h1 = __floats2half2_rn(a1.x, a1.y);
                uint2 pk;
                pk.x = *reinterpret_cast<unsigned*>(&h0);
                pk.y = *reinterpret_cast<unsigned*>(&h1);
                *reinterpret_cast<uint2*>(g_uh + ((size_t)b * NN + jg) * KK + kbase) = pk;
                fadd2(s0[bb][0], acc[bb][0]);
                fadd2(s0[bb][1], acc[bb][1]);
                acc[bb][0] = acc[bb][1] = 0ull;
            }
        }
#undef PADDR
    }

    const float sc = 1.0f / 32.0f;         // softmax(0) coupling = 1/C
    const size_t kbase = (size_t)kq * 256 + (size_t)kg * 4;
#pragma unroll
    for (int bb = 0; bb < 8; bb++) {
        const int b = bg * 8 + bb;
        float2 a0 = up2(s0[bb][0]), a1 = up2(s0[bb][1]);
        float4 r = make_float4(a0.x * sc, a0.y * sc, a1.x * sc, a1.y * sc);
        *reinterpret_cast<float4*>(
            g_s0p + ((size_t)b * NCH1 + chunk) * KK + kbase) = r;
    }
}

// Routing pass v4. Lane t's uint4 group q (index t+32q of the u row) covers
// k = 8t+256q+e (e<8), all in capsule c_q = (t>>2)+8q. Quad shfl (xor 1,2)
// completes each capsule logit; shfl xor 4/8/16 spans the 32 capsules for
// the softmax. v held as fp16x2 REGISTERS (16 regs); u rows kept raw and
// converted on the fly (no 32-reg uf array). TWO rows per body with
// interleaved softmax chains. ~120 regs -> 2 CTAs/SM, zero LDS in the loop.
// NP=1: logits = u.v0.   NP=2: logits = u.(v0+v1).
template <int NP>
__global__ void __launch_bounds__(256, 2)
k_pass(const float* __restrict__ vin0, const float* __restrict__ vin1,
       float* __restrict__ sp) {
    const int b = blockIdx.y;
    const int w = threadIdx.x >> 5;
    const int t = threadIdx.x & 31;

    __shared__ float red[8][1032];     // CTA reduction (16B-aligned rows)

    // v as half2 registers at the u k-mapping (NP==2 folds v0+v1)
    __half2 vh[16];
#pragma unroll
    for (int q = 0; q < 4; q++) {
        float4 a = *reinterpret_cast<const float4*>(vin0 + (size_t)b * KK + 8 * t + 256 * q);
        float4 c4 = *reinterpret_cast<const float4*>(vin0 + (size_t)b * KK + 8 * t + 256 * q + 4);
        if (NP == 2) {
            float4 a1 = *reinterpret_cast<const float4*>(vin1 + (size_t)b * KK + 8 * t + 256 * q);
            float4 c1 = *reinterpret_cast<const float4*>(vin1 + (size_t)b * KK + 8 * t + 256 * q + 4);
            a.x += a1.x; a.y += a1.y; a.z += a1.z; a.w += a1.w;
            c4.x += c1.x; c4.y += c1.y; c4.z += c1.z; c4.w += c1.w;
        }
        vh[q * 4 + 0] = __floats2half2_rn(a.x, a.y);
        vh[q * 4 + 1] = __floats2half2_rn(a.z, a.w);
        vh[q * 4 + 2] = __floats2half2_rn(c4.x, c4.y);
        vh[q * 4 + 3] = __floats2half2_rn(c4.z, c4.w);
    }

    float sacc[32];
#pragma unroll
    for (int l = 0; l < 32; l++) sacc[l] = 0.f;

    const int jbase = blockIdx.x * 64 + w * 8;   // 8 warps x 8 j = 64 j / CTA
    const uint4* up = reinterpret_cast<const uint4*>(g_uh + ((size_t)b * NN + jbase) * KK);

    uint4 raw0[4], raw1[4];
#pragma unroll
    for (int q = 0; q < 4; q++) raw0[q] = up[q * 32 + t];          // j0
#pragma unroll
    for (int q = 0; q < 4; q++) raw1[q] = up[128 + q * 32 + t];    // j1

    for (int jb = 0; jb < 8; jb += 2) {
        // free raw0 early: copy, then prefetch j+2 into it
        uint4 cpy0[4];
#pragma unroll
        for (int q = 0; q < 4; q++) cpy0[q] = raw0[q];
        if (jb + 2 < 8) {
#pragma unroll
            for (int q = 0; q < 4; q++) raw0[q] = up[(jb + 2) * 128 + q * 32 + t];
        }

        // logits for both rows (HFMA2 dot), interleaved
        float d0[4], d1[4];
#pragma unroll
        for (int q = 0; q < 4; q++) {
            __half2 a0 = __float2half2_rn(0.f), a1 = __float2half2_rn(0.f);
#pragma unroll
            for (int p = 0; p < 4; p++) {
                a0 = __hfma2(geth2(cpy0[q], p), vh[q * 4 + p], a0);
                a1 = __hfma2(geth2(raw1[q], p), vh[q * 4 + p], a1);
            }
            float2 f0 = __half22float2(a0), f1 = __half22float2(a1);
            d0[q] = f0.x + f0.y;
            d1[q] = f1.x + f1.y;
            d0[q] += __shfl_xor_sync(0xffffffffu, d0[q], 1);
            d1[q] += __shfl_xor_sync(0xffffffffu, d1[q], 1);
            d0[q] += __shfl_xor_sync(0xffffffffu, d0[q], 2);
            d1[q] += __shfl_xor_sync(0xffffffffu, d1[q], 2);
        }

        // softmax over 32 capsules, two independent chains interleaved
        float m0 = fmaxf(fmaxf(d0[0], d0[1]), fmaxf(d0[2], d0[3]));
        float m1 = fmaxf(fmaxf(d1[0], d1[1]), fmaxf(d1[2], d1[3]));
        m0 = fmaxf(m0, __shfl_xor_sync(0xffffffffu, m0, 4));
        m1 = fmaxf(m1, __shfl_xor_sync(0xffffffffu, m1, 4));
        m0 = fmaxf(m0, __shfl_xor_sync(0xffffffffu, m0, 8));
        m1 = fmaxf(m1, __shfl_xor_sync(0xffffffffu, m1, 8));
        m0 = fmaxf(m0, __shfl_xor_sync(0xffffffffu, m0, 16));
        m1 = fmaxf(m1, __shfl_xor_sync(0xffffffffu, m1, 16));

        float ce0[4], ce1[4];
#pragma unroll
        for (int q = 0; q < 4; q++) {
            ce0[q] = __expf(d0[q] - m0);
            ce1[q] = __expf(d1[q] - m1);
        }
        float Z0 = (ce0[0] + ce0[1]) + (ce0[2] + ce0[3]);
        float Z1 = (ce1[0] + ce1[1]) + (ce1[2] + ce1[3]);
        Z0 += __shfl_xor_sync(0xffffffffu, Z0, 4);
        Z1 += __shfl_xor_sync(0xffffffffu, Z1, 4);
        Z0 += __shfl_xor_sync(0xffffffffu, Z0, 8);
        Z1 += __shfl_xor_sync(0xffffffffu, Z1, 8);
        Z0 += __shfl_xor_sync(0xffffffffu, Z0, 16);
        Z1 += __shfl_xor_sync(0xffffffffu, Z1, 16);
        const float i0 = __fdividef(1.0f, Z0);
        const float i1 = __fdividef(1.0f, Z1);

        // accumulate both rows (cvt on the fly)
#pragma unroll
        for (int q = 0; q < 4; q++) {
            const float c0 = ce0[q] * i0;
            const float c1 = ce1[q] * i1;
#pragma unroll
            for (int p = 0; p < 4; p++) {
                float2 f = __half22float2(geth2(cpy0[q], p));
                sacc[8 * q + 2 * p]     += c0 * f.x;
                sacc[8 * q + 2 * p + 1] += c0 * f.y;
                f = __half22float2(geth2(raw1[q], p));
                sacc[8 * q + 2 * p]     += c1 * f.x;
                sacc[8 * q + 2 * p + 1] += c1 * f.y;
            }
        }

        // raw1 now free: prefetch j+3
        if (jb + 3 < 8) {
#pragma unroll
            for (int q = 0; q < 4; q++) raw1[q] = up[(jb + 3) * 128 + q * 32 + t];
        }
    }

    // CTA reduction across the 8 warps (natural k layout)
#pragma unroll
    for (int q = 0; q < 4; q++) {
        *reinterpret_cast<float4*>(&red[w][8 * t + 256 * q])     =
            make_float4(sacc[8 * q + 0], sacc[8 * q + 1], sacc[8 * q + 2], sacc[8 * q + 3]);
        *reinterpret_cast<float4*>(&red[w][8 * t + 256 * q + 4]) =
            make_float4(sacc[8 * q + 4], sacc[8 * q + 5], sacc[8 * q + 6], sacc[8 * q + 7]);
    }
    __syncthreads();

    float4 s = make_float4(0.f, 0.f, 0.f, 0.f);
#pragma unroll
    for (int ww = 0; ww < 8; ww++) {
        float4 p = *reinterpret_cast<const float4*>(&red[ww][4 * threadIdx.x]);
        s.x += p.x; s.y += p.y; s.z += p.z; s.w += p.w;
    }
    *reinterpret_cast<float4*>(sp + ((size_t)b * PCH + blockIdx.x) * KK + 4 * threadIdx.x) = s;
}

// Finalize: reduce NCH chunk partials + biases, squash -> v.
// One CTA (8 warps) per (b,c) for memory-level parallelism on the reduction.
template <int NCH>
__global__ void __launch_bounds__(256)
k_fin(const float* __restrict__ sp, const float* __restrict__ biases,
      float* __restrict__ vout) {
    const int bc = blockIdx.x;
    const int b = bc >> 5, c = bc & 31;
    const int w = threadIdx.x >> 5, lane = threadIdx.x & 31;

    float s = 0.f;
    const float* p = sp + (size_t)b * NCH * KK + c * LL + lane;
#pragma unroll 8
    for (int n = w; n < NCH; n += 8) s += p[(size_t)n * KK];

    __shared__ float red[8][32];
    red[w][lane] = s;
    __syncthreads();

    if (w == 0) {
        float v = biases[c * LL + lane];
#pragma unroll
        for (int ww = 0; ww < 8; ww++) v += red[ww][lane];
        float n2 = v * v;
#pragma unroll
        for (int o = 16; o; o >>= 1) n2 += __shfl_xor_sync(0xffffffffu, n2, o);
        const float nn = sqrtf(n2);
        const float f = n2 / (1.0f + n2) / (nn + 1e-7f);   // squash factor
        vout[(size_t)b * KK + c * LL + lane] = f * v;
    }
}

extern "C" void kernel_launch(void* const* d_in, const int* in_sizes, int n_in,
                              void* d_out, int out_size) {
    const float* x      = (const float*)d_in[0];  // [32,8,8,32,32] = [B,N,iL]
    const float* Wt     = (const float*)d_in[1];  // [2048,32,1024]
    const float* biases = (const float*)d_in[2];  // [32,32]
    float* out = (float*)d_out;                   // [32,32,32]

    float *s0p, *sp, *v0, *v1, *dm;
    cudaGetSymbolAddress((void**)&s0p, g_s0p);
    cudaGetSymbolAddress((void**)&sp,  g_sp);
    cudaGetSymbolAddress((void**)&v0,  g_v0);
    cudaGetSymbolAddress((void**)&v1,  g_v1);
    cudaGetSymbolAddress((void**)&dm,  g_dummy);

    // 3 dummies: puts k1 at the slot ncu's skip lands on (pass<1> was
    // profiled at my-index-3 last round with 1 dummy).
    k_dummy<<<1, 32>>>(dm);                              // 0
    k_dummy<<<1, 32>>>(dm);                              // 1
    k_dummy<<<1, 32>>>(dm);                              // 2
    k1<<<dim3(NCH1, 4), 256>>>(x, Wt);                   // 3 <- profiled
    k_fin<NCH1><<<BB * CC, 256>>>(s0p, biases, v0);      // 4
    k_pass<1><<<dim3(PCH, BB), 256>>>(v0, v0, sp);       // 5
    k_fin<PCH><<<BB * CC, 256>>>(sp, biases, v1);        // 6
    k_pass<2><<<dim3(PCH, BB), 256>>>(v0, v1, sp);       // 7
    k_fin<PCH><<<BB * CC, 256>>>(sp, biases, out);       // 8
}